// round 4
// baseline (speedup 1.0000x reference)
#include <cuda_runtime.h>

// GraphSAGE 3-layer GCN aggregator. N=100000, E=1600000, 64->64->64->40.
//
// Restructure: ((segsum(h[src]) + h) * inv) @ W^T + b
//            = (segsum(p[src])  + p) * inv + b   with p = h @ W^T
// Pipeline:
//   CSR build: deg -> 3-kernel scan -> fill (esrc grouped by dst)
//   k0: p0 = feats @ W0^T                         (gemmf, no pre-activation)
//   g1: agg0 = self + gather(p0)                  (raw sums)
//   k1: p1 = relu(agg0*inv + b0) @ W1^T           (gemmf, fused finalize)
//   g2: agg1 = self + gather(p1)
//   k2: p2 = relu(agg1*inv + b1) @ W2^T  (40w)
//   g3: out = (self + gather(p2))*inv + b2        (gather w/ fused finalize)
// Gather: 16 lanes/node, float4/lane; indices loaded 16-at-a-time and
// broadcast via shfl(width=16) -> 16 independent LDG.128 in flight.

constexpr int NN = 100000;
constexpr int NE = 1600000;
constexpr int NB = (NN + 1023) / 1024;  // 98 scan blocks

__device__ float g_pA[NN * 64];
__device__ float g_pB[NN * 64];
__device__ float g_agg[NN * 64];
__device__ int   g_deg[NN];
__device__ int   g_off[NN + 1];
__device__ int   g_cur[NN];
__device__ int   g_esrc[NE];
__device__ int   g_bsum[NB];
__device__ int   g_boff[NB];

// ---------------------------------------------------------------- degrees ---
__global__ void deg_zero_k() {
    int i = blockIdx.x * 256 + threadIdx.x;
    if (i < NN) g_deg[i] = 0;
}

__global__ void deg_count_k(const int4* __restrict__ dst4) {
    int i = blockIdx.x * 256 + threadIdx.x;
    if (i < NE / 4) {
        int4 d = __ldg(&dst4[i]);
        atomicAdd(&g_deg[d.x], 1);
        atomicAdd(&g_deg[d.y], 1);
        atomicAdd(&g_deg[d.z], 1);
        atomicAdd(&g_deg[d.w], 1);
    }
}

// ------------------------------------------------------------------- scan ---
__global__ __launch_bounds__(1024) void scan_bsum_k() {
    int i = blockIdx.x * 1024 + threadIdx.x;
    int v = (i < NN) ? g_deg[i] : 0;
#pragma unroll
    for (int o = 16; o; o >>= 1) v += __shfl_down_sync(~0u, v, o);
    __shared__ int ws[32];
    if ((threadIdx.x & 31) == 0) ws[threadIdx.x >> 5] = v;
    __syncthreads();
    if (threadIdx.x < 32) {
        int s = ws[threadIdx.x];
#pragma unroll
        for (int o = 16; o; o >>= 1) s += __shfl_down_sync(~0u, s, o);
        if (threadIdx.x == 0) g_bsum[blockIdx.x] = s;
    }
}

__global__ void scan_partials_k() {  // 1 block x 128 (NB=98 <= 128)
    int t = threadIdx.x;
    int v = (t < NB) ? g_bsum[t] : 0;
    int lane = t & 31, w = t >> 5;
    int x = v;
#pragma unroll
    for (int o = 1; o < 32; o <<= 1) {
        int y = __shfl_up_sync(~0u, x, o);
        if (lane >= o) x += y;
    }
    __shared__ int wsum[4];
    if (lane == 31) wsum[w] = x;
    __syncthreads();
    int add = 0;
    for (int j = 0; j < w; j++) add += wsum[j];
    if (t < NB) g_boff[t] = x + add - v;  // exclusive
}

__global__ __launch_bounds__(1024) void scan_write_k() {
    int i = blockIdx.x * 1024 + threadIdx.x;
    int v = (i < NN) ? g_deg[i] : 0;
    int lane = threadIdx.x & 31, w = threadIdx.x >> 5;
    int x = v;
#pragma unroll
    for (int o = 1; o < 32; o <<= 1) {
        int y = __shfl_up_sync(~0u, x, o);
        if (lane >= o) x += y;
    }
    __shared__ int ws[32], sws[32];
    if (lane == 31) ws[w] = x;
    __syncthreads();
    if (threadIdx.x < 32) {
        int s = ws[threadIdx.x];
        int xx = s;
#pragma unroll
        for (int o = 1; o < 32; o <<= 1) {
            int y = __shfl_up_sync(~0u, xx, o);
            if (lane >= o) xx += y;
        }
        sws[threadIdx.x] = xx - s;  // exclusive warp prefix
    }
    __syncthreads();
    int incl = x + sws[w] + g_boff[blockIdx.x];
    int excl = incl - v;
    if (i < NN) {
        g_off[i] = excl;
        g_cur[i] = excl;
        if (i == NN - 1) g_off[NN] = incl;
    }
}

// ------------------------------------------------------------------- fill ---
__global__ void fill_k(const int4* __restrict__ src4,
                       const int4* __restrict__ dst4) {
    int i = blockIdx.x * 256 + threadIdx.x;
    if (i < NE / 4) {
        int4 s = __ldg(&src4[i]);
        int4 d = __ldg(&dst4[i]);
        g_esrc[atomicAdd(&g_cur[d.x], 1)] = s.x;
        g_esrc[atomicAdd(&g_cur[d.y], 1)] = s.y;
        g_esrc[atomicAdd(&g_cur[d.z], 1)] = s.z;
        g_esrc[atomicAdd(&g_cur[d.w], 1)] = s.w;
    }
}

// ------------------------------------------------------------------ gemmf ---
// pout[n,o] = sum_k hrow[n,k] * W[o,k], where
//   hrow = PRE ? relu(in[n,:]*inv_n + bpre) : in[n,:]
// Block (64, 8) = 512 threads, 64 nodes per block; W in per-thread registers.
template <int DOUT, bool PRE>
__global__ __launch_bounds__(512) void gemmf_k(const float* __restrict__ in,
                                               const float* __restrict__ W,
                                               const float* __restrict__ bpre,
                                               float* __restrict__ pout) {
    __shared__ float Ws[64 * 65];
    __shared__ float hs[8][65];
    const int tx = threadIdx.x, ty = threadIdx.y;
    const int tid = ty * 64 + tx;
    for (int i = tid; i < DOUT * 64; i += 512)
        Ws[(i >> 6) * 65 + (i & 63)] = W[i];
    __syncthreads();
    float w[64];
    if (tx < DOUT) {
#pragma unroll
        for (int k = 0; k < 64; k++) w[k] = Ws[tx * 65 + k];
    }

    const int base = blockIdx.x * 64;
#pragma unroll
    for (int it = 0; it < 8; it++) {
        int n = base + it * 8 + ty;
        __syncthreads();
        if (n < NN) {
            float v = in[n * 64 + tx];
            if (PRE) {
                float inv = 1.f / (float)(__ldg(&g_off[n + 1]) - __ldg(&g_off[n]) + 1);
                v = fmaxf(fmaf(v, inv, __ldg(&bpre[tx])), 0.f);
            }
            hs[ty][tx] = v;
        }
        __syncthreads();
        if (n < NN && tx < DOUT) {
            float acc = 0.f;
#pragma unroll
            for (int k = 0; k < 64; k++) acc = fmaf(hs[ty][k], w[k], acc);
            pout[n * DOUT + tx] = acc;
        }
    }
}

// ----------------------------------------------------------------- gather ---
// agg[n,:] = pin[n,:] + sum_{e in CSR row n} pin[esrc[e],:]
// If FIN: out = agg*inv + bias (final layer, no relu).
// 512 threads = 32 node-groups x 16 lanes; float4 per lane. Indices fetched
// 16-at-a-time by the group, broadcast via shfl(width 16) -> high load MLP.
template <int L4, bool FIN>
__global__ __launch_bounds__(512) void gather_k(const float4* __restrict__ pin,
                                                float4* __restrict__ outp,
                                                const float4* __restrict__ bias) {
    const int tid = threadIdx.x;
    const int g = tid >> 4;
    const int q = tid & 15;
    const int node = blockIdx.x * 32 + g;  // grid exact: 3125*32 = 100000

    const int s0 = __ldg(&g_off[node]);
    const int s1 = __ldg(&g_off[node + 1]);
    const int trips = (s1 - s0 + 15) >> 4;
    const int tmax = max(trips, __shfl_xor_sync(~0u, trips, 16));

    float4 a0 = make_float4(0.f, 0.f, 0.f, 0.f);
    float4 a1 = make_float4(0.f, 0.f, 0.f, 0.f);
    if (q < L4) a0 = __ldg(&pin[node * L4 + q]);  // self term

    for (int t = 0; t < tmax; t++) {
        int base = s0 + (t << 4);
        int idx = 0;
        if (base + q < s1) idx = __ldg(&g_esrc[base + q]);
#pragma unroll
        for (int j = 0; j < 16; j += 2) {
            int sa = __shfl_sync(~0u, idx, j, 16);
            int sb = __shfl_sync(~0u, idx, j + 1, 16);
            float4 va = make_float4(0.f, 0.f, 0.f, 0.f);
            float4 vb = make_float4(0.f, 0.f, 0.f, 0.f);
            if (q < L4 && base + j < s1)     va = __ldg(&pin[sa * L4 + q]);
            if (q < L4 && base + j + 1 < s1) vb = __ldg(&pin[sb * L4 + q]);
            a0.x += va.x; a0.y += va.y; a0.z += va.z; a0.w += va.w;
            a1.x += vb.x; a1.y += vb.y; a1.z += vb.z; a1.w += vb.w;
        }
    }
    a0.x += a1.x; a0.y += a1.y; a0.z += a1.z; a0.w += a1.w;

    if (q < L4) {
        if (FIN) {
            float inv = 1.f / (float)(s1 - s0 + 1);
            float4 bb = __ldg(&bias[q]);
            a0.x = fmaf(a0.x, inv, bb.x);
            a0.y = fmaf(a0.y, inv, bb.y);
            a0.z = fmaf(a0.z, inv, bb.z);
            a0.w = fmaf(a0.w, inv, bb.w);
        }
        outp[node * L4 + q] = a0;
    }
}

// ----------------------------------------------------------------- launch ---
extern "C" void kernel_launch(void* const* d_in, const int* in_sizes, int n_in,
                              void* d_out, int out_size) {
    const float* feats = (const float*)d_in[0];
    const int*   src   = (const int*)d_in[1];
    const int*   dst   = (const int*)d_in[2];
    const float* W0 = (const float*)d_in[3];
    const float* b0 = (const float*)d_in[4];
    const float* W1 = (const float*)d_in[5];
    const float* b1 = (const float*)d_in[6];
    const float* W2 = (const float*)d_in[7];
    const float* b2 = (const float*)d_in[8];
    float* out = (float*)d_out;

    void *pA_v = nullptr, *pB_v = nullptr, *agg_v = nullptr;
    cudaGetSymbolAddress(&pA_v, g_pA);
    cudaGetSymbolAddress(&pB_v, g_pB);
    cudaGetSymbolAddress(&agg_v, g_agg);
    float* pA = (float*)pA_v;
    float* pB = (float*)pB_v;
    float* agg = (float*)agg_v;

    // CSR build
    deg_zero_k<<<(NN + 255) / 256, 256>>>();
    deg_count_k<<<(NE / 4 + 255) / 256, 256>>>((const int4*)dst);
    scan_bsum_k<<<NB, 1024>>>();
    scan_partials_k<<<1, 128>>>();
    scan_write_k<<<NB, 1024>>>();
    fill_k<<<(NE / 4 + 255) / 256, 256>>>((const int4*)src, (const int4*)dst);

    const int GB_G = NN / 32;        // 3125 (exact)
    const int GB_M = (NN + 63) / 64; // 1563
    const dim3 MB(64, 8);

    // k0: p0 = feats @ W0^T
    gemmf_k<64, false><<<GB_M, MB>>>(feats, W0, nullptr, pA);
    // g1 + k1
    gather_k<16, false><<<GB_G, 512>>>((const float4*)pA, (float4*)agg, nullptr);
    gemmf_k<64, true><<<GB_M, MB>>>(agg, W1, b0, pB);
    // g2 + k2
    gather_k<16, false><<<GB_G, 512>>>((const float4*)pB, (float4*)agg, nullptr);
    gemmf_k<40, true><<<GB_M, MB>>>(agg, W2, b1, pA);
    // g3 (fused finalize) -> out
    gather_k<10, true><<<GB_G, 512>>>((const float4*)pA, (float4*)out,
                                      (const float4*)b2);
}